// round 4
// baseline (speedup 1.0000x reference)
#include <cuda_runtime.h>
#include <math.h>

#define EPSV 1e-5f

// ---------------- scratch (no cudaMalloc allowed) ----------------
__device__ float g_h1[4 * 128 * 64 * 64];       // conv1 out, NCHW
__device__ float g_h2[4 * 64 * 64 * 256];       // conv2 out, NHWC
__device__ float g_im[16384 * 1152];            // im2col scratch (reused)
__device__ float g_s[4 * 1024 * 256];           // sequence
__device__ float g_xr[4 * 1024 * 1024];         // in_proj out (xi | res)
__device__ float g_xl[4 * 1024 * 512];          // after dw conv
__device__ float g_xdbl[4 * 1024 * 64];         // x_proj out (dt|B|C)
__device__ float g_delta[4 * 1024 * 512];
__device__ float g_y[4 * 1024 * 512];           // scan out * silu(res)
__device__ float g_y2[4 * 1024 * 256];          // out_proj out
__device__ float g_poolp[4 * 16 * 256];         // partial pool sums
__device__ float g_pool[4 * 256];

__device__ __forceinline__ float gelu_f(float x) {
    return 0.5f * x * (1.f + erff(x * 0.70710678118654752f));
}

// ---------------- conv1: 3->128, 3x3 pad1, + BN + GELU ----------------
__global__ void conv1_kernel(const float* __restrict__ x, const float* __restrict__ w,
                             const float* __restrict__ cb, const float* __restrict__ g,
                             const float* __restrict__ bb) {
    int idx = blockIdx.x * blockDim.x + threadIdx.x;
    if (idx >= 4 * 128 * 64 * 64) return;
    int xo = idx & 63;
    int yo = (idx >> 6) & 63;
    int oc = (idx >> 12) & 127;
    int b  = idx >> 19;
    float acc = cb[oc];
    #pragma unroll
    for (int ic = 0; ic < 3; ic++) {
        #pragma unroll
        for (int ky = 0; ky < 3; ky++) {
            int iy = yo + ky - 1;
            if (iy < 0 || iy > 63) continue;
            #pragma unroll
            for (int kx = 0; kx < 3; kx++) {
                int ix = xo + kx - 1;
                if (ix < 0 || ix > 63) continue;
                acc = fmaf(x[((b * 3 + ic) * 64 + iy) * 64 + ix],
                           w[((oc * 3 + ic) * 3 + ky) * 3 + kx], acc);
            }
        }
    }
    acc = acc * (g[oc] * rsqrtf(1.f + EPSV)) + bb[oc];
    g_h1[idx] = gelu_f(acc);
}

// ---------------- im2col for conv2 (3x3 pad1 on h1 NCHW) ----------------
__global__ void im2col2_kernel() {
    int idx = blockIdx.x * blockDim.x + threadIdx.x;
    if (idx >= 16384 * 1152) return;
    int col = idx % 1152;
    int row = idx / 1152;
    int ic = col / 9;
    int r = col % 9;
    int ky = r / 3, kx = r % 3;
    int x_ = row & 63;
    int y_ = (row >> 6) & 63;
    int b  = row >> 12;
    int iy = y_ + ky - 1, ix = x_ + kx - 1;
    float v = 0.f;
    if (iy >= 0 && iy < 64 && ix >= 0 && ix < 64)
        v = g_h1[((b * 128 + ic) * 64 + iy) * 64 + ix];
    g_im[idx] = v;
}

// ---------------- im2col for conv3 (2x2 s2 on h2 NHWC) ----------------
__global__ void im2col3_kernel() {
    int idx = blockIdx.x * blockDim.x + threadIdx.x;
    if (idx >= 4096 * 1024) return;
    int col = idx & 1023;
    int row = idx >> 10;
    int ic = col >> 2;
    int r = col & 3;
    int ky = r >> 1, kx = r & 1;
    int ox = row & 31;
    int oy = (row >> 5) & 31;
    int b  = row >> 10;
    g_im[idx] = g_h2[((b * 64 + 2 * oy + ky) * 64 + 2 * ox + kx) * 256 + ic];
}

// ---------------- register-blocked double-buffered SGEMM ----------------
// C[M,N] = A[M,K](lda) @ W[N,K]^T (+bias, epilogue)
// act: 0 none, 1 softplus, 2 BN+GELU
template <int BM, int BN>
__global__ void __launch_bounds__(256)
gemm2_kernel(const float* __restrict__ A, int lda,
             const float* __restrict__ W,
             const float* __restrict__ bias,
             const float* __restrict__ bng,
             const float* __restrict__ bnb,
             float* __restrict__ C, int ldc,
             int K, int act) {
    constexpr int BK = 8;
    constexpr int TM = BM / 16;
    constexpr int TN = BN / 16;
    __shared__ __align__(16) float As[2][BK][BM];
    __shared__ __align__(16) float Ws[2][BK][BN];
    int tid = threadIdx.x;
    int tx = tid & 15, ty = tid >> 4;
    int bm = blockIdx.y * BM, bn = blockIdx.x * BN;
    int aRow = tid >> 1;
    int aK = (tid & 1) * 4;
    bool aAct = aRow < BM;
    bool wAct = aRow < BN;
    const float* Ap = A + (size_t)(bm + aRow) * lda + aK;
    const float* Wp = W + (size_t)(bn + aRow) * K + aK;

    float4 av = make_float4(0, 0, 0, 0), wv = make_float4(0, 0, 0, 0);
    if (aAct) av = *(const float4*)Ap;
    if (wAct) wv = *(const float4*)Wp;
    if (aAct) {
        As[0][aK + 0][aRow] = av.x; As[0][aK + 1][aRow] = av.y;
        As[0][aK + 2][aRow] = av.z; As[0][aK + 3][aRow] = av.w;
    }
    if (wAct) {
        Ws[0][aK + 0][aRow] = wv.x; Ws[0][aK + 1][aRow] = wv.y;
        Ws[0][aK + 2][aRow] = wv.z; Ws[0][aK + 3][aRow] = wv.w;
    }
    __syncthreads();

    float acc[TM][TN];
    #pragma unroll
    for (int i = 0; i < TM; i++)
        #pragma unroll
        for (int j = 0; j < TN; j++) acc[i][j] = 0.f;

    int nT = K / BK;
    for (int t = 0; t < nT; t++) {
        int buf = t & 1;
        if (t + 1 < nT) {
            if (aAct) av = *(const float4*)(Ap + (t + 1) * BK);
            if (wAct) wv = *(const float4*)(Wp + (t + 1) * BK);
        }
        #pragma unroll
        for (int kk = 0; kk < BK; kk++) {
            float ar[TM], br[TN];
            #pragma unroll
            for (int i = 0; i < TM; i += 4)
                *(float4*)&ar[i] = *(const float4*)&As[buf][kk][ty * TM + i];
            #pragma unroll
            for (int j = 0; j < TN; j += 4)
                *(float4*)&br[j] = *(const float4*)&Ws[buf][kk][tx * TN + j];
            #pragma unroll
            for (int i = 0; i < TM; i++)
                #pragma unroll
                for (int j = 0; j < TN; j++)
                    acc[i][j] = fmaf(ar[i], br[j], acc[i][j]);
        }
        if (t + 1 < nT) {
            int nb = buf ^ 1;
            if (aAct) {
                As[nb][aK + 0][aRow] = av.x; As[nb][aK + 1][aRow] = av.y;
                As[nb][aK + 2][aRow] = av.z; As[nb][aK + 3][aRow] = av.w;
            }
            if (wAct) {
                Ws[nb][aK + 0][aRow] = wv.x; Ws[nb][aK + 1][aRow] = wv.y;
                Ws[nb][aK + 2][aRow] = wv.z; Ws[nb][aK + 3][aRow] = wv.w;
            }
            __syncthreads();
        }
    }

    #pragma unroll
    for (int j = 0; j < TN; j++) {
        int nn = bn + tx * TN + j;
        float bj = bias ? bias[nn] : 0.f;
        float gj = 0.f, bbj = 0.f;
        if (act == 2) { gj = bng[nn] * rsqrtf(1.f + EPSV); bbj = bnb[nn]; }
        #pragma unroll
        for (int i = 0; i < TM; i++) {
            int m = bm + ty * TM + i;
            float v = acc[i][j] + bj;
            if (act == 1) v = (v > 20.f) ? v : log1pf(expf(v));
            else if (act == 2) v = gelu_f(v * gj + bbj);
            C[(size_t)m * ldc + nn] = v;
        }
    }
}

// ---------------- depthwise conv1d K=4, pad (1,2), over xi = xr[:, :, 0:512] --------
__global__ void dwconv_kernel(const float* __restrict__ cw, const float* __restrict__ cb) {
    int idx = blockIdx.x * blockDim.x + threadIdx.x;
    if (idx >= 4 * 1024 * 512) return;
    int d = idx & 511;
    int l = (idx >> 9) & 1023;
    int b = idx >> 19;
    float acc = cb[d];
    #pragma unroll
    for (int k = 0; k < 4; k++) {
        int l2 = l - 1 + k;
        if (l2 >= 0 && l2 < 1024)
            acc = fmaf(cw[d * 4 + k], g_xr[(b * 1024 + l2) * 1024 + d], acc);
    }
    g_xl[(b * 1024 + l) * 512 + d] = acc;
}

// ---------------- selective scan: 16 lanes per (b,d), one state n per lane ----------
__global__ void scan_kernel(const float* __restrict__ alog, const float* __restrict__ dssm) {
    int t = blockIdx.x * blockDim.x + threadIdx.x;
    int grp = t >> 4;
    int n = t & 15;
    if (grp >= 4 * 512) return;
    int b = grp >> 9;
    int d = grp & 511;
    float Areg = -__expf(alog[d * 16 + n]);
    float Dd = dssm[d];
    float h = 0.f;
    const float* drow = g_delta + (b * 1024) * 512 + d;
    const float* urow = g_xl + (b * 1024) * 512 + d;
    const float* brow = g_xdbl + (b * 1024) * 64 + 32 + n;
    const float* crow = g_xdbl + (b * 1024) * 64 + 48 + n;
    const float* rrow = g_xr + (b * 1024) * 1024 + 512 + d;
    float* yrow = g_y + (b * 1024) * 512 + d;
    for (int l0 = 0; l0 < 1024; l0 += 4) {
        float dv[4], uv[4], Bv[4], Cv[4];
        #pragma unroll
        for (int j = 0; j < 4; j++) {
            int l = l0 + j;
            dv[j] = drow[l * 512];
            uv[j] = urow[l * 512];
            Bv[j] = brow[l * 64];
            Cv[j] = crow[l * 64];
        }
        #pragma unroll
        for (int j = 0; j < 4; j++) {
            float a = __expf(dv[j] * Areg);
            h = fmaf(a, h, dv[j] * Bv[j] * uv[j]);
            float p = h * Cv[j];
            p += __shfl_xor_sync(0xffffffffu, p, 8);
            p += __shfl_xor_sync(0xffffffffu, p, 4);
            p += __shfl_xor_sync(0xffffffffu, p, 2);
            p += __shfl_xor_sync(0xffffffffu, p, 1);
            if (n == 0) {
                int l = l0 + j;
                float r = rrow[l * 1024];
                float sil = r / (1.f + __expf(-r));
                yrow[l * 512] = (p + uv[j] * Dd) * sil;
            }
        }
    }
}

// ---------------- LayerNorm(256) + residual into s ----------------
__global__ void lnres_kernel(const float* __restrict__ yin, const float* __restrict__ g,
                             const float* __restrict__ bb) {
    int row = blockIdx.x;
    int c = threadIdx.x;
    __shared__ float red[256];
    float v = yin[row * 256 + c];
    red[c] = v;
    __syncthreads();
    for (int st = 128; st > 0; st >>= 1) {
        if (c < st) red[c] += red[c + st];
        __syncthreads();
    }
    float mean = red[0] * (1.f / 256.f);
    __syncthreads();
    float dv = v - mean;
    red[c] = dv * dv;
    __syncthreads();
    for (int st = 128; st > 0; st >>= 1) {
        if (c < st) red[c] += red[c + st];
        __syncthreads();
    }
    float var = red[0] * (1.f / 256.f);
    g_s[row * 256 + c] += dv * rsqrtf(var + EPSV) * g[c] + bb[c];
}

// ---------------- mean pool over L, two-stage ----------------
__global__ void pool_partial_kernel() {
    int b = blockIdx.x;
    int chunk = blockIdx.y;
    int c = threadIdx.x;
    float acc = 0.f;
    int l0 = chunk * 64;
    for (int l = l0; l < l0 + 64; l++) acc += g_s[(b * 1024 + l) * 256 + c];
    g_poolp[(b * 16 + chunk) * 256 + c] = acc;
}

// ---------------- head LN (reduces partials) ----------------
__global__ void headln_kernel(const float* __restrict__ nw, const float* __restrict__ nb) {
    int b = blockIdx.x;
    int c = threadIdx.x;
    __shared__ float red[256];
    float v = 0.f;
    #pragma unroll
    for (int k = 0; k < 16; k++) v += g_poolp[(b * 16 + k) * 256 + c];
    v *= (1.f / 1024.f);
    red[c] = v;
    __syncthreads();
    for (int st = 128; st > 0; st >>= 1) {
        if (c < st) red[c] += red[c + st];
        __syncthreads();
    }
    float mean = red[0] * (1.f / 256.f);
    __syncthreads();
    float dv = v - mean;
    red[c] = dv * dv;
    __syncthreads();
    for (int st = 128; st > 0; st >>= 1) {
        if (c < st) red[c] += red[c + st];
        __syncthreads();
    }
    float var = red[0] * (1.f / 256.f);
    g_pool[b * 256 + c] = dv * rsqrtf(var + EPSV) * nw[c] + nb[c];
}

// ---------------- FC: logits ----------------
__global__ void fc_kernel(const float* __restrict__ fcw, const float* __restrict__ fcb,
                          float* __restrict__ out) {
    int idx = blockIdx.x * blockDim.x + threadIdx.x;
    if (idx >= 4000) return;
    int b = idx / 1000;
    int nn = idx % 1000;
    float acc = fcb[nn];
    for (int k = 0; k < 256; k++)
        acc = fmaf(g_pool[b * 256 + k], fcw[nn * 256 + k], acc);
    out[idx] = acc;
}

// ---------------- softmax over 1000 ----------------
__global__ void softmax_kernel(const float* __restrict__ logits, float* __restrict__ out) {
    int b = blockIdx.x;
    int t = threadIdx.x;
    __shared__ float red[256];
    float mx = -1e30f;
    for (int i = t; i < 1000; i += 256) mx = fmaxf(mx, logits[b * 1000 + i]);
    red[t] = mx;
    __syncthreads();
    for (int st = 128; st > 0; st >>= 1) {
        if (t < st) red[t] = fmaxf(red[t], red[t + st]);
        __syncthreads();
    }
    mx = red[0];
    __syncthreads();
    float sum = 0.f;
    for (int i = t; i < 1000; i += 256) sum += expf(logits[b * 1000 + i] - mx);
    red[t] = sum;
    __syncthreads();
    for (int st = 128; st > 0; st >>= 1) {
        if (t < st) red[t] += red[t + st];
        __syncthreads();
    }
    float inv = 1.f / red[0];
    for (int i = t; i < 1000; i += 256)
        out[b * 1000 + i] = expf(logits[b * 1000 + i] - mx) * inv;
}

// ---------------- host ----------------
template <int BM, int BN>
static void launch_gemm2(const float* A, int lda, const float* W, const float* bias,
                         const float* bng, const float* bnb, float* C, int ldc,
                         int M, int N, int K, int act) {
    dim3 grid(N / BN, M / BM);
    gemm2_kernel<BM, BN><<<grid, 256>>>(A, lda, W, bias, bng, bnb, C, ldc, K, act);
}

extern "C" void kernel_launch(void* const* d_in, const int* in_sizes, int n_in,
                              void* d_out, int out_size) {
    const float* x    = (const float*)d_in[0];
    const float* c1w  = (const float*)d_in[1];
    const float* c1b  = (const float*)d_in[2];
    const float* g1   = (const float*)d_in[3];
    const float* b1   = (const float*)d_in[4];
    const float* c2w  = (const float*)d_in[5];
    const float* c2b  = (const float*)d_in[6];
    const float* g2   = (const float*)d_in[7];
    const float* b2   = (const float*)d_in[8];
    const float* pw   = (const float*)d_in[9];
    const float* pb   = (const float*)d_in[10];
    const float* g3   = (const float*)d_in[11];
    const float* b3   = (const float*)d_in[12];
    const float* ipw  = (const float*)d_in[13];
    const float* ipb  = (const float*)d_in[14];
    const float* cw   = (const float*)d_in[15];
    const float* cb   = (const float*)d_in[16];
    const float* xpw  = (const float*)d_in[17];
    const float* dpw  = (const float*)d_in[18];
    const float* dpb  = (const float*)d_in[19];
    const float* alog = (const float*)d_in[20];
    const float* dssm = (const float*)d_in[21];
    const float* opw  = (const float*)d_in[22];
    const float* opb  = (const float*)d_in[23];
    const float* lnw  = (const float*)d_in[24];
    const float* lnb  = (const float*)d_in[25];
    const float* nw   = (const float*)d_in[26];
    const float* nb   = (const float*)d_in[27];
    const float* fcw  = (const float*)d_in[28];
    const float* fcb  = (const float*)d_in[29];

    float *im, *h2, *s, *xr, *xl, *xdbl, *delta, *y, *y2;
    cudaGetSymbolAddress((void**)&im, g_im);
    cudaGetSymbolAddress((void**)&h2, g_h2);
    cudaGetSymbolAddress((void**)&s, g_s);
    cudaGetSymbolAddress((void**)&xr, g_xr);
    cudaGetSymbolAddress((void**)&xl, g_xl);
    cudaGetSymbolAddress((void**)&xdbl, g_xdbl);
    cudaGetSymbolAddress((void**)&delta, g_delta);
    cudaGetSymbolAddress((void**)&y, g_y);
    cudaGetSymbolAddress((void**)&y2, g_y2);

    // conv stem
    conv1_kernel<<<8192, 256>>>(x, c1w, c1b, g1, b1);
    im2col2_kernel<<<73728, 256>>>();
    launch_gemm2<128, 128>(im, 1152, c2w, c2b, g2, b2, h2, 256, 16384, 256, 1152, 2);
    im2col3_kernel<<<16384, 256>>>();
    launch_gemm2<128, 64>(im, 1024, pw, pb, g3, b3, s, 256, 4096, 256, 1024, 2);

    // mamba blocks
    for (int i = 0; i < 4; i++) {
        launch_gemm2<128, 128>(s, 256, ipw + i * 1024 * 256, ipb + i * 1024, 0, 0,
                               xr, 1024, 4096, 1024, 256, 0);
        dwconv_kernel<<<8192, 256>>>(cw + i * 512 * 4, cb + i * 512);
        launch_gemm2<64, 64>(xl, 512, xpw + i * 64 * 512, 0, 0, 0,
                             xdbl, 64, 4096, 64, 512, 0);
        launch_gemm2<128, 64>(xdbl, 64, dpw + i * 512 * 32, dpb + i * 512, 0, 0,
                              delta, 512, 4096, 512, 32, 1);
        scan_kernel<<<128, 256>>>(alog + i * 512 * 16, dssm + i * 512);
        launch_gemm2<128, 64>(y, 512, opw + i * 256 * 512, opb + i * 256, 0, 0,
                              y2, 256, 4096, 256, 512, 0);
        lnres_kernel<<<4096, 256>>>(y2, lnw + i * 256, lnb + i * 256);
    }

    // head
    dim3 pgrid(4, 16);
    pool_partial_kernel<<<pgrid, 256>>>();
    headln_kernel<<<4, 256>>>(nw, nb);
    float* out = (float*)d_out;
    fc_kernel<<<16, 256>>>(fcw, fcb, out);
    softmax_kernel<<<4, 256>>>(out, out + 4000);
}

// round 6
// speedup vs baseline: 1.1052x; 1.1052x over previous
#include <cuda_runtime.h>
#include <math.h>

#define EPSV 1e-5f

// ---------------- scratch (no cudaMalloc allowed) ----------------
__device__ float g_h1[4 * 128 * 64 * 64];       // conv1 out, NCHW
__device__ float g_h2[4 * 64 * 64 * 256];       // conv2 out, NHWC
__device__ float g_im[16384 * 1152];            // im2col scratch (reused)
__device__ float g_s[4 * 1024 * 256];           // sequence
__device__ float g_xr[4 * 1024 * 1024];         // in_proj out (xi | res)
__device__ float g_xl[4 * 1024 * 512];          // after dw conv
__device__ float g_xdbl[4 * 1024 * 64];         // x_proj out (dt|B|C)
__device__ float g_delta[4 * 1024 * 512];
__device__ float g_y[4 * 1024 * 512];           // scan out * silu(res)
__device__ float g_y2[4 * 1024 * 256];          // out_proj out
__device__ float g_poolp[4 * 16 * 256];         // partial pool sums
__device__ float g_pool[4 * 256];

__device__ __forceinline__ float gelu_f(float x) {
    return 0.5f * x * (1.f + erff(x * 0.70710678118654752f));
}

// ---------------- conv1: 3->128, 3x3 pad1, + BN + GELU ----------------
__global__ void conv1_kernel(const float* __restrict__ x, const float* __restrict__ w,
                             const float* __restrict__ cb, const float* __restrict__ g,
                             const float* __restrict__ bb) {
    int idx = blockIdx.x * blockDim.x + threadIdx.x;
    if (idx >= 4 * 128 * 64 * 64) return;
    int xo = idx & 63;
    int yo = (idx >> 6) & 63;
    int oc = (idx >> 12) & 127;
    int b  = idx >> 19;
    float acc = cb[oc];
    #pragma unroll
    for (int ic = 0; ic < 3; ic++) {
        #pragma unroll
        for (int ky = 0; ky < 3; ky++) {
            int iy = yo + ky - 1;
            if (iy < 0 || iy > 63) continue;
            #pragma unroll
            for (int kx = 0; kx < 3; kx++) {
                int ix = xo + kx - 1;
                if (ix < 0 || ix > 63) continue;
                acc = fmaf(x[((b * 3 + ic) * 64 + iy) * 64 + ix],
                           w[((oc * 3 + ic) * 3 + ky) * 3 + kx], acc);
            }
        }
    }
    acc = acc * (g[oc] * rsqrtf(1.f + EPSV)) + bb[oc];
    g_h1[idx] = gelu_f(acc);
}

// ---------------- im2col for conv2 (3x3 pad1 on h1 NCHW) ----------------
__global__ void im2col2_kernel() {
    int idx = blockIdx.x * blockDim.x + threadIdx.x;
    if (idx >= 16384 * 1152) return;
    int col = idx % 1152;
    int row = idx / 1152;
    int ic = col / 9;
    int r = col % 9;
    int ky = r / 3, kx = r % 3;
    int x_ = row & 63;
    int y_ = (row >> 6) & 63;
    int b  = row >> 12;
    int iy = y_ + ky - 1, ix = x_ + kx - 1;
    float v = 0.f;
    if (iy >= 0 && iy < 64 && ix >= 0 && ix < 64)
        v = g_h1[((b * 128 + ic) * 64 + iy) * 64 + ix];
    g_im[idx] = v;
}

// ---------------- im2col for conv3 (2x2 s2 on h2 NHWC) ----------------
__global__ void im2col3_kernel() {
    int idx = blockIdx.x * blockDim.x + threadIdx.x;
    if (idx >= 4096 * 1024) return;
    int col = idx & 1023;
    int row = idx >> 10;
    int ic = col >> 2;
    int r = col & 3;
    int ky = r >> 1, kx = r & 1;
    int ox = row & 31;
    int oy = (row >> 5) & 31;
    int b  = row >> 10;
    g_im[idx] = g_h2[((b * 64 + 2 * oy + ky) * 64 + 2 * ox + kx) * 256 + ic];
}

// ---------------- warp-tiled, conflict-free, double-buffered SGEMM ----------------
// C[M,N] = A[M,K](lda) @ W[N,K]^T (+bias, epilogue).  act: 0 none, 1 softplus, 2 BN+GELU
// 256 threads = 8 warps in 2(m) x 4(n) grid; lanes 8(m) x 4(n); per-thread TMxTN in
// 4x4 quadrants.  Fragment loads are lane_m*4 / lane_n*4 float4s -> broadcast,
// conflict-free smem reads.
template <int BM, int BN>
__global__ void __launch_bounds__(256)
gemm3_kernel(const float* __restrict__ A, int lda,
             const float* __restrict__ W,
             const float* __restrict__ bias,
             const float* __restrict__ bng,
             const float* __restrict__ bnb,
             float* __restrict__ C, int ldc,
             int K, int act) {
    constexpr int BK = 8;
    constexpr int TM = BM / 16;          // 8 (BM=128) or 4 (BM=64)
    constexpr int TN = BN / 16;
    constexpr int QM = TM / 4;           // quadrant counts
    constexpr int QN = TN / 4;
    __shared__ __align__(16) float As[2][BK][BM];
    __shared__ __align__(16) float Ws[2][BK][BN];
    int tid = threadIdx.x;
    int wid = tid >> 5, lane = tid & 31;
    int wm = wid >> 2, wn = wid & 3;     // warp grid 2x4
    int lm = lane >> 2, ln = lane & 3;   // lane grid 8x4
    int bm = blockIdx.y * BM, bn = blockIdx.x * BN;

    int aRow = tid >> 1;
    int aK = (tid & 1) * 4;
    bool aAct = aRow < BM;
    bool wAct = aRow < BN;
    const float* Ap = A + (size_t)(bm + (aAct ? aRow : 0)) * lda + aK;
    const float* Wp = W + (size_t)(bn + (wAct ? aRow : 0)) * K + aK;

    float4 av = make_float4(0, 0, 0, 0), wv = make_float4(0, 0, 0, 0);
    if (aAct) av = *(const float4*)Ap;
    if (wAct) wv = *(const float4*)Wp;
    if (aAct) {
        As[0][aK + 0][aRow] = av.x; As[0][aK + 1][aRow] = av.y;
        As[0][aK + 2][aRow] = av.z; As[0][aK + 3][aRow] = av.w;
    }
    if (wAct) {
        Ws[0][aK + 0][aRow] = wv.x; Ws[0][aK + 1][aRow] = wv.y;
        Ws[0][aK + 2][aRow] = wv.z; Ws[0][aK + 3][aRow] = wv.w;
    }
    __syncthreads();

    float acc[TM][TN];
    #pragma unroll
    for (int i = 0; i < TM; i++)
        #pragma unroll
        for (int j = 0; j < TN; j++) acc[i][j] = 0.f;

    int nT = K / BK;
    for (int t = 0; t < nT; t++) {
        int buf = t & 1;
        if (t + 1 < nT) {
            if (aAct) av = *(const float4*)(Ap + (t + 1) * BK);
            if (wAct) wv = *(const float4*)(Wp + (t + 1) * BK);
        }
        #pragma unroll
        for (int kk = 0; kk < BK; kk++) {
            float ar[TM], br[TN];
            #pragma unroll
            for (int q = 0; q < QM; q++)
                *(float4*)&ar[q * 4] =
                    *(const float4*)&As[buf][kk][wm * (BM / 2) + q * (BM / 4) + lm * 4];
            #pragma unroll
            for (int q = 0; q < QN; q++)
                *(float4*)&br[q * 4] =
                    *(const float4*)&Ws[buf][kk][wn * (BN / 4) + q * (BN / 8) + ln * 4];
            #pragma unroll
            for (int i = 0; i < TM; i++)
                #pragma unroll
                for (int j = 0; j < TN; j++)
                    acc[i][j] = fmaf(ar[i], br[j], acc[i][j]);
        }
        if (t + 1 < nT) {
            int nb = buf ^ 1;
            if (aAct) {
                As[nb][aK + 0][aRow] = av.x; As[nb][aK + 1][aRow] = av.y;
                As[nb][aK + 2][aRow] = av.z; As[nb][aK + 3][aRow] = av.w;
            }
            if (wAct) {
                Ws[nb][aK + 0][aRow] = wv.x; Ws[nb][aK + 1][aRow] = wv.y;
                Ws[nb][aK + 2][aRow] = wv.z; Ws[nb][aK + 3][aRow] = wv.w;
            }
            __syncthreads();
        }
    }

    // epilogue: vectorized float4 stores per (row, n-quadrant)
    #pragma unroll
    for (int qn = 0; qn < QN; qn++) {
        int n0 = bn + wn * (BN / 4) + qn * (BN / 8) + ln * 4;
        float bj[4], gj[4], bbj[4];
        #pragma unroll
        for (int j = 0; j < 4; j++) {
            bj[j] = bias ? bias[n0 + j] : 0.f;
            if (act == 2) {
                gj[j] = bng[n0 + j] * rsqrtf(1.f + EPSV);
                bbj[j] = bnb[n0 + j];
            }
        }
        #pragma unroll
        for (int qm = 0; qm < QM; qm++) {
            #pragma unroll
            for (int i = 0; i < 4; i++) {
                int m = bm + wm * (BM / 2) + qm * (BM / 4) + lm * 4 + i;
                float4 o;
                float* op = (float*)&o;
                #pragma unroll
                for (int j = 0; j < 4; j++) {
                    float v = acc[qm * 4 + i][qn * 4 + j] + bj[j];
                    if (act == 1) v = (v > 20.f) ? v : log1pf(expf(v));
                    else if (act == 2) v = gelu_f(v * gj[j] + bbj[j]);
                    op[j] = v;
                }
                *(float4*)&C[(size_t)m * ldc + n0] = o;
            }
        }
    }
}

// ---------------- depthwise conv1d K=4, pad (1,2), over xi = xr[:, :, 0:512] --------
__global__ void dwconv_kernel(const float* __restrict__ cw, const float* __restrict__ cb) {
    int idx = blockIdx.x * blockDim.x + threadIdx.x;
    if (idx >= 4 * 1024 * 512) return;
    int d = idx & 511;
    int l = (idx >> 9) & 1023;
    int b = idx >> 19;
    float acc = cb[d];
    #pragma unroll
    for (int k = 0; k < 4; k++) {
        int l2 = l - 1 + k;
        if (l2 >= 0 && l2 < 1024)
            acc = fmaf(cw[d * 4 + k], g_xr[(b * 1024 + l2) * 1024 + d], acc);
    }
    g_xl[(b * 1024 + l) * 512 + d] = acc;
}

// ---------------- selective scan: 16 lanes per (b,d), one state n per lane ----------
__global__ void scan_kernel(const float* __restrict__ alog, const float* __restrict__ dssm) {
    int t = blockIdx.x * blockDim.x + threadIdx.x;
    int grp = t >> 4;
    int n = t & 15;
    if (grp >= 4 * 512) return;
    int b = grp >> 9;
    int d = grp & 511;
    float Areg = -__expf(alog[d * 16 + n]);
    float Dd = dssm[d];
    float h = 0.f;
    const float* drow = g_delta + (b * 1024) * 512 + d;
    const float* urow = g_xl + (b * 1024) * 512 + d;
    const float* brow = g_xdbl + (b * 1024) * 64 + 32 + n;
    const float* crow = g_xdbl + (b * 1024) * 64 + 48 + n;
    const float* rrow = g_xr + (b * 1024) * 1024 + 512 + d;
    float* yrow = g_y + (b * 1024) * 512 + d;
    for (int l0 = 0; l0 < 1024; l0 += 4) {
        float dv[4], uv[4], Bv[4], Cv[4];
        #pragma unroll
        for (int j = 0; j < 4; j++) {
            int l = l0 + j;
            dv[j] = drow[l * 512];
            uv[j] = urow[l * 512];
            Bv[j] = brow[l * 64];
            Cv[j] = crow[l * 64];
        }
        #pragma unroll
        for (int j = 0; j < 4; j++) {
            float a = __expf(dv[j] * Areg);
            h = fmaf(a, h, dv[j] * Bv[j] * uv[j]);
            float p = h * Cv[j];
            p += __shfl_xor_sync(0xffffffffu, p, 8);
            p += __shfl_xor_sync(0xffffffffu, p, 4);
            p += __shfl_xor_sync(0xffffffffu, p, 2);
            p += __shfl_xor_sync(0xffffffffu, p, 1);
            if (n == 0) {
                int l = l0 + j;
                float r = rrow[l * 1024];
                float sil = r / (1.f + __expf(-r));
                yrow[l * 512] = (p + uv[j] * Dd) * sil;
            }
        }
    }
}

// ---------------- LayerNorm(256) + residual into s ----------------
__global__ void lnres_kernel(const float* __restrict__ yin, const float* __restrict__ g,
                             const float* __restrict__ bb) {
    int row = blockIdx.x;
    int c = threadIdx.x;
    __shared__ float red[256];
    float v = yin[row * 256 + c];
    red[c] = v;
    __syncthreads();
    for (int st = 128; st > 0; st >>= 1) {
        if (c < st) red[c] += red[c + st];
        __syncthreads();
    }
    float mean = red[0] * (1.f / 256.f);
    __syncthreads();
    float dv = v - mean;
    red[c] = dv * dv;
    __syncthreads();
    for (int st = 128; st > 0; st >>= 1) {
        if (c < st) red[c] += red[c + st];
        __syncthreads();
    }
    float var = red[0] * (1.f / 256.f);
    g_s[row * 256 + c] += dv * rsqrtf(var + EPSV) * g[c] + bb[c];
}

// ---------------- mean pool over L, two-stage ----------------
__global__ void pool_partial_kernel() {
    int b = blockIdx.x;
    int chunk = blockIdx.y;
    int c = threadIdx.x;
    float acc = 0.f;
    int l0 = chunk * 64;
    for (int l = l0; l < l0 + 64; l++) acc += g_s[(b * 1024 + l) * 256 + c];
    g_poolp[(b * 16 + chunk) * 256 + c] = acc;
}

// ---------------- head LN (reduces partials) ----------------
__global__ void headln_kernel(const float* __restrict__ nw, const float* __restrict__ nb) {
    int b = blockIdx.x;
    int c = threadIdx.x;
    __shared__ float red[256];
    float v = 0.f;
    #pragma unroll
    for (int k = 0; k < 16; k++) v += g_poolp[(b * 16 + k) * 256 + c];
    v *= (1.f / 1024.f);
    red[c] = v;
    __syncthreads();
    for (int st = 128; st > 0; st >>= 1) {
        if (c < st) red[c] += red[c + st];
        __syncthreads();
    }
    float mean = red[0] * (1.f / 256.f);
    __syncthreads();
    float dv = v - mean;
    red[c] = dv * dv;
    __syncthreads();
    for (int st = 128; st > 0; st >>= 1) {
        if (c < st) red[c] += red[c + st];
        __syncthreads();
    }
    float var = red[0] * (1.f / 256.f);
    g_pool[b * 256 + c] = dv * rsqrtf(var + EPSV) * nw[c] + nb[c];
}

// ---------------- FC: logits (vectorized) ----------------
__global__ void fc_kernel(const float* __restrict__ fcw, const float* __restrict__ fcb,
                          float* __restrict__ out) {
    int idx = blockIdx.x * blockDim.x + threadIdx.x;
    if (idx >= 4000) return;
    int b = idx / 1000;
    int nn = idx % 1000;
    const float4* wp = (const float4*)(fcw + nn * 256);
    const float4* pp = (const float4*)(g_pool + b * 256);
    float acc = fcb[nn];
    #pragma unroll 8
    for (int k = 0; k < 64; k++) {
        float4 w4 = wp[k], p4 = pp[k];
        acc = fmaf(w4.x, p4.x, acc);
        acc = fmaf(w4.y, p4.y, acc);
        acc = fmaf(w4.z, p4.z, acc);
        acc = fmaf(w4.w, p4.w, acc);
    }
    out[idx] = acc;
}

// ---------------- softmax over 1000 ----------------
__global__ void softmax_kernel(const float* __restrict__ logits, float* __restrict__ out) {
    int b = blockIdx.x;
    int t = threadIdx.x;
    __shared__ float red[256];
    float mx = -1e30f;
    for (int i = t; i < 1000; i += 256) mx = fmaxf(mx, logits[b * 1000 + i]);
    red[t] = mx;
    __syncthreads();
    for (int st = 128; st > 0; st >>= 1) {
        if (t < st) red[t] = fmaxf(red[t], red[t + st]);
        __syncthreads();
    }
    mx = red[0];
    __syncthreads();
    float sum = 0.f;
    for (int i = t; i < 1000; i += 256) sum += expf(logits[b * 1000 + i] - mx);
    red[t] = sum;
    __syncthreads();
    for (int st = 128; st > 0; st >>= 1) {
        if (t < st) red[t] += red[t + st];
        __syncthreads();
    }
    float inv = 1.f / red[0];
    for (int i = t; i < 1000; i += 256)
        out[b * 1000 + i] = expf(logits[b * 1000 + i] - mx) * inv;
}

// ---------------- host ----------------
template <int BM, int BN>
static void launch_gemm3(const float* A, int lda, const float* W, const float* bias,
                         const float* bng, const float* bnb, float* C, int ldc,
                         int M, int N, int K, int act) {
    dim3 grid(N / BN, M / BM);
    gemm3_kernel<BM, BN><<<grid, 256>>>(A, lda, W, bias, bng, bnb, C, ldc, K, act);
}

extern "C" void kernel_launch(void* const* d_in, const int* in_sizes, int n_in,
                              void* d_out, int out_size) {
    const float* x    = (const float*)d_in[0];
    const float* c1w  = (const float*)d_in[1];
    const float* c1b  = (const float*)d_in[2];
    const float* g1   = (const float*)d_in[3];
    const float* b1   = (const float*)d_in[4];
    const float* c2w  = (const float*)d_in[5];
    const float* c2b  = (const float*)d_in[6];
    const float* g2   = (const float*)d_in[7];
    const float* b2   = (const float*)d_in[8];
    const float* pw   = (const float*)d_in[9];
    const float* pb   = (const float*)d_in[10];
    const float* g3   = (const float*)d_in[11];
    const float* b3   = (const float*)d_in[12];
    const float* ipw  = (const float*)d_in[13];
    const float* ipb  = (const float*)d_in[14];
    const float* cw   = (const float*)d_in[15];
    const float* cb   = (const float*)d_in[16];
    const float* xpw  = (const float*)d_in[17];
    const float* dpw  = (const float*)d_in[18];
    const float* dpb  = (const float*)d_in[19];
    const float* alog = (const float*)d_in[20];
    const float* dssm = (const float*)d_in[21];
    const float* opw  = (const float*)d_in[22];
    const float* opb  = (const float*)d_in[23];
    const float* lnw  = (const float*)d_in[24];
    const float* lnb  = (const float*)d_in[25];
    const float* nw   = (const float*)d_in[26];
    const float* nb   = (const float*)d_in[27];
    const float* fcw  = (const float*)d_in[28];
    const float* fcb  = (const float*)d_in[29];

    float *im, *h2, *s, *xr, *xl, *xdbl, *delta, *y, *y2;
    cudaGetSymbolAddress((void**)&im, g_im);
    cudaGetSymbolAddress((void**)&h2, g_h2);
    cudaGetSymbolAddress((void**)&s, g_s);
    cudaGetSymbolAddress((void**)&xr, g_xr);
    cudaGetSymbolAddress((void**)&xl, g_xl);
    cudaGetSymbolAddress((void**)&xdbl, g_xdbl);
    cudaGetSymbolAddress((void**)&delta, g_delta);
    cudaGetSymbolAddress((void**)&y, g_y);
    cudaGetSymbolAddress((void**)&y2, g_y2);

    // conv stem
    conv1_kernel<<<8192, 256>>>(x, c1w, c1b, g1, b1);
    im2col2_kernel<<<73728, 256>>>();
    launch_gemm3<128, 128>(im, 1152, c2w, c2b, g2, b2, h2, 256, 16384, 256, 1152, 2);
    im2col3_kernel<<<16384, 256>>>();
    launch_gemm3<64, 128>(im, 1024, pw, pb, g3, b3, s, 256, 4096, 256, 1024, 2);

    // mamba blocks
    for (int i = 0; i < 4; i++) {
        launch_gemm3<128, 128>(s, 256, ipw + i * 1024 * 256, ipb + i * 1024, 0, 0,
                               xr, 1024, 4096, 1024, 256, 0);
        dwconv_kernel<<<8192, 256>>>(cw + i * 512 * 4, cb + i * 512);
        launch_gemm3<64, 64>(xl, 512, xpw + i * 64 * 512, 0, 0, 0,
                             xdbl, 64, 4096, 64, 512, 0);
        launch_gemm3<128, 64>(xdbl, 64, dpw + i * 512 * 32, dpb + i * 512, 0, 0,
                              delta, 512, 4096, 512, 32, 1);
        scan_kernel<<<128, 256>>>(alog + i * 512 * 16, dssm + i * 512);
        launch_gemm3<64, 128>(y, 512, opw + i * 256 * 512, opb + i * 256, 0, 0,
                              y2, 256, 4096, 256, 512, 0);
        lnres_kernel<<<4096, 256>>>(y2, lnw + i * 256, lnb + i * 256);
    }

    // head
    dim3 pgrid(4, 16);
    pool_partial_kernel<<<pgrid, 256>>>();
    headln_kernel<<<4, 256>>>(nw, nb);
    float* out = (float*)d_out;
    fc_kernel<<<16, 256>>>(fcw, fcb, out);
    softmax_kernel<<<4, 256>>>(out, out + 4000);
}

// round 7
// speedup vs baseline: 1.1854x; 1.0725x over previous
#include <cuda_runtime.h>
#include <math.h>

#define EPSV 1e-5f

typedef unsigned long long u64;

__device__ __forceinline__ u64 pack2(float lo, float hi) {
    u64 r; asm("mov.b64 %0, {%1, %2};" : "=l"(r) : "f"(lo), "f"(hi)); return r;
}
__device__ __forceinline__ u64 fma2(u64 a, u64 b, u64 c) {
    u64 d; asm("fma.rn.f32x2 %0, %1, %2, %3;" : "=l"(d) : "l"(a), "l"(b), "l"(c)); return d;
}
__device__ __forceinline__ void unpack2(u64 v, float& lo, float& hi) {
    asm("mov.b64 {%0, %1}, %2;" : "=f"(lo), "=f"(hi) : "l"(v));
}

// ---------------- scratch (no cudaMalloc allowed) ----------------
__device__ float g_h1[4 * 128 * 64 * 64];       // conv1 out, NCHW
__device__ float g_h2[4 * 64 * 64 * 256];       // conv2 out, NHWC
__device__ float g_im[16384 * 1152];            // im2col scratch (reused)
__device__ float g_s[4 * 1024 * 256];           // sequence
__device__ float g_xr[4 * 1024 * 1024];         // in_proj out (xi | res)
__device__ float g_xl[4 * 1024 * 512];          // after dw conv
__device__ float g_xdbl[4 * 1024 * 64];         // x_proj out (dt|B|C)
__device__ float g_delta[4 * 1024 * 512];
__device__ float g_y[4 * 1024 * 512];           // scan out * silu(res)
__device__ float g_y2[4 * 1024 * 256];          // out_proj out
__device__ float g_poolp[4 * 16 * 256];         // partial pool sums
__device__ float g_pool[4 * 256];

__device__ __forceinline__ float gelu_f(float x) {
    return 0.5f * x * (1.f + erff(x * 0.70710678118654752f));
}

// ---------------- conv1: 3->128, 3x3 pad1, + BN + GELU ----------------
__global__ void conv1_kernel(const float* __restrict__ x, const float* __restrict__ w,
                             const float* __restrict__ cb, const float* __restrict__ g,
                             const float* __restrict__ bb) {
    int idx = blockIdx.x * blockDim.x + threadIdx.x;
    if (idx >= 4 * 128 * 64 * 64) return;
    int xo = idx & 63;
    int yo = (idx >> 6) & 63;
    int oc = (idx >> 12) & 127;
    int b  = idx >> 19;
    float acc = cb[oc];
    #pragma unroll
    for (int ic = 0; ic < 3; ic++) {
        #pragma unroll
        for (int ky = 0; ky < 3; ky++) {
            int iy = yo + ky - 1;
            if (iy < 0 || iy > 63) continue;
            #pragma unroll
            for (int kx = 0; kx < 3; kx++) {
                int ix = xo + kx - 1;
                if (ix < 0 || ix > 63) continue;
                acc = fmaf(x[((b * 3 + ic) * 64 + iy) * 64 + ix],
                           w[((oc * 3 + ic) * 3 + ky) * 3 + kx], acc);
            }
        }
    }
    acc = acc * (g[oc] * rsqrtf(1.f + EPSV)) + bb[oc];
    g_h1[idx] = gelu_f(acc);
}

// ---------------- im2col for conv2 (3x3 pad1 on h1 NCHW) ----------------
__global__ void im2col2_kernel() {
    int idx = blockIdx.x * blockDim.x + threadIdx.x;
    if (idx >= 16384 * 1152) return;
    int col = idx % 1152;
    int row = idx / 1152;
    int ic = col / 9;
    int r = col % 9;
    int ky = r / 3, kx = r % 3;
    int x_ = row & 63;
    int y_ = (row >> 6) & 63;
    int b  = row >> 12;
    int iy = y_ + ky - 1, ix = x_ + kx - 1;
    float v = 0.f;
    if (iy >= 0 && iy < 64 && ix >= 0 && ix < 64)
        v = g_h1[((b * 128 + ic) * 64 + iy) * 64 + ix];
    g_im[idx] = v;
}

// ---------------- im2col for conv3 (2x2 s2 on h2 NHWC) ----------------
__global__ void im2col3_kernel() {
    int idx = blockIdx.x * blockDim.x + threadIdx.x;
    if (idx >= 4096 * 1024) return;
    int col = idx & 1023;
    int row = idx >> 10;
    int ic = col >> 2;
    int r = col & 3;
    int ky = r >> 1, kx = r & 1;
    int ox = row & 31;
    int oy = (row >> 5) & 31;
    int b  = row >> 10;
    g_im[idx] = g_h2[((b * 64 + 2 * oy + ky) * 64 + 2 * ox + kx) * 256 + ic];
}

// ---------------- warp-tiled, conflict-free, double-buffered SGEMM + FFMA2 ---------
// C[M,N] = A[M,K](lda) @ W[N,K]^T (+bias, epilogue).  act: 0 none, 1 softplus, 2 BN+GELU
template <int BM, int BN>
__global__ void __launch_bounds__(256)
gemm4_kernel(const float* __restrict__ A, int lda,
             const float* __restrict__ W,
             const float* __restrict__ bias,
             const float* __restrict__ bng,
             const float* __restrict__ bnb,
             float* __restrict__ C, int ldc,
             int K, int act) {
    constexpr int BK = 8;
    constexpr int TM = BM / 16;          // 8 (BM=128) or 4 (BM=64)
    constexpr int TN = BN / 16;
    constexpr int QM = TM / 4;
    constexpr int QN = TN / 4;
    constexpr int TN2 = TN / 2;
    __shared__ __align__(16) float As[2][BK][BM];
    __shared__ __align__(16) float Ws[2][BK][BN];
    int tid = threadIdx.x;
    int wid = tid >> 5, lane = tid & 31;
    int wm = wid >> 2, wn = wid & 3;     // warp grid 2x4
    int lm = lane >> 2, ln = lane & 3;   // lane grid 8x4
    int bm = blockIdx.y * BM, bn = blockIdx.x * BN;

    int aRow = tid >> 1;
    int aK = (tid & 1) * 4;
    bool aAct = aRow < BM;
    bool wAct = aRow < BN;
    const float* Ap = A + (size_t)(bm + (aAct ? aRow : 0)) * lda + aK;
    const float* Wp = W + (size_t)(bn + (wAct ? aRow : 0)) * K + aK;

    float4 av = make_float4(0, 0, 0, 0), wv = make_float4(0, 0, 0, 0);
    if (aAct) av = *(const float4*)Ap;
    if (wAct) wv = *(const float4*)Wp;
    if (aAct) {
        As[0][aK + 0][aRow] = av.x; As[0][aK + 1][aRow] = av.y;
        As[0][aK + 2][aRow] = av.z; As[0][aK + 3][aRow] = av.w;
    }
    if (wAct) {
        Ws[0][aK + 0][aRow] = wv.x; Ws[0][aK + 1][aRow] = wv.y;
        Ws[0][aK + 2][aRow] = wv.z; Ws[0][aK + 3][aRow] = wv.w;
    }
    __syncthreads();

    u64 acc2[TM][TN2];
    #pragma unroll
    for (int i = 0; i < TM; i++)
        #pragma unroll
        for (int j = 0; j < TN2; j++) acc2[i][j] = pack2(0.f, 0.f);

    int nT = K / BK;
    for (int t = 0; t < nT; t++) {
        int buf = t & 1;
        if (t + 1 < nT) {
            if (aAct) av = *(const float4*)(Ap + (t + 1) * BK);
            if (wAct) wv = *(const float4*)(Wp + (t + 1) * BK);
        }
        #pragma unroll
        for (int kk = 0; kk < BK; kk++) {
            float ar[TM], br[TN];
            #pragma unroll
            for (int q = 0; q < QM; q++)
                *(float4*)&ar[q * 4] =
                    *(const float4*)&As[buf][kk][wm * (BM / 2) + q * (BM / 4) + lm * 4];
            #pragma unroll
            for (int q = 0; q < QN; q++)
                *(float4*)&br[q * 4] =
                    *(const float4*)&Ws[buf][kk][wn * (BN / 4) + q * (BN / 8) + ln * 4];
            u64 bp[TN2];
            #pragma unroll
            for (int j = 0; j < TN2; j++) bp[j] = pack2(br[2 * j], br[2 * j + 1]);
            #pragma unroll
            for (int i = 0; i < TM; i++) {
                u64 ap = pack2(ar[i], ar[i]);
                #pragma unroll
                for (int j = 0; j < TN2; j++)
                    acc2[i][j] = fma2(ap, bp[j], acc2[i][j]);
            }
        }
        if (t + 1 < nT) {
            int nb = buf ^ 1;
            if (aAct) {
                As[nb][aK + 0][aRow] = av.x; As[nb][aK + 1][aRow] = av.y;
                As[nb][aK + 2][aRow] = av.z; As[nb][aK + 3][aRow] = av.w;
            }
            if (wAct) {
                Ws[nb][aK + 0][aRow] = wv.x; Ws[nb][aK + 1][aRow] = wv.y;
                Ws[nb][aK + 2][aRow] = wv.z; Ws[nb][aK + 3][aRow] = wv.w;
            }
            __syncthreads();
        }
    }

    // unpack accumulators
    float acc[TM][TN];
    #pragma unroll
    for (int i = 0; i < TM; i++)
        #pragma unroll
        for (int j = 0; j < TN2; j++)
            unpack2(acc2[i][j], acc[i][2 * j], acc[i][2 * j + 1]);

    // epilogue: vectorized float4 stores per (row, n-quadrant)
    #pragma unroll
    for (int qn = 0; qn < QN; qn++) {
        int n0 = bn + wn * (BN / 4) + qn * (BN / 8) + ln * 4;
        float bj[4], gj[4], bbj[4];
        #pragma unroll
        for (int j = 0; j < 4; j++) {
            bj[j] = bias ? bias[n0 + j] : 0.f;
            if (act == 2) {
                gj[j] = bng[n0 + j] * rsqrtf(1.f + EPSV);
                bbj[j] = bnb[n0 + j];
            }
        }
        #pragma unroll
        for (int qm = 0; qm < QM; qm++) {
            #pragma unroll
            for (int i = 0; i < 4; i++) {
                int m = bm + wm * (BM / 2) + qm * (BM / 4) + lm * 4 + i;
                float4 o;
                float* op = (float*)&o;
                #pragma unroll
                for (int j = 0; j < 4; j++) {
                    float v = acc[qm * 4 + i][qn * 4 + j] + bj[j];
                    if (act == 1) v = (v > 20.f) ? v : log1pf(expf(v));
                    else if (act == 2) v = gelu_f(v * gj[j] + bbj[j]);
                    op[j] = v;
                }
                *(float4*)&C[(size_t)m * ldc + n0] = o;
            }
        }
    }
}

// ---------------- depthwise conv1d K=4, pad (1,2), over xi = xr[:, :, 0:512] --------
__global__ void dwconv_kernel(const float* __restrict__ cw, const float* __restrict__ cb) {
    int idx = blockIdx.x * blockDim.x + threadIdx.x;
    if (idx >= 4 * 1024 * 512) return;
    int d = idx & 511;
    int l = (idx >> 9) & 1023;
    int b = idx >> 19;
    float acc = cb[d];
    #pragma unroll
    for (int k = 0; k < 4; k++) {
        int l2 = l - 1 + k;
        if (l2 >= 0 && l2 < 1024)
            acc = fmaf(cw[d * 4 + k], g_xr[(b * 1024 + l2) * 1024 + d], acc);
    }
    g_xl[(b * 1024 + l) * 512 + d] = acc;
}

// ---------------- selective scan: 16 lanes per (b,d), interleaved reductions --------
__global__ void scan_kernel(const float* __restrict__ alog, const float* __restrict__ dssm) {
    int t = blockIdx.x * blockDim.x + threadIdx.x;
    int grp = t >> 4;
    int n = t & 15;
    if (grp >= 4 * 512) return;
    int b = grp >> 9;
    int d = grp & 511;
    float Areg = -__expf(alog[d * 16 + n]);
    float Dd = dssm[d];
    float h = 0.f;
    const float* drow = g_delta + (b * 1024) * 512 + d;
    const float* urow = g_xl + (b * 1024) * 512 + d;
    const float* brow = g_xdbl + (b * 1024) * 64 + 32 + n;
    const float* crow = g_xdbl + (b * 1024) * 64 + 48 + n;
    const float* rrow = g_xr + (b * 1024) * 1024 + 512 + d;
    float* yrow = g_y + (b * 1024) * 512 + d;
    for (int l0 = 0; l0 < 1024; l0 += 4) {
        float dv[4], uv[4], Bv[4], Cv[4], av[4], p[4];
        #pragma unroll
        for (int j = 0; j < 4; j++) {
            int l = l0 + j;
            dv[j] = drow[l * 512];
            uv[j] = urow[l * 512];
            Bv[j] = brow[l * 64];
            Cv[j] = crow[l * 64];
        }
        #pragma unroll
        for (int j = 0; j < 4; j++) av[j] = __expf(dv[j] * Areg);
        #pragma unroll
        for (int j = 0; j < 4; j++) {
            h = fmaf(av[j], h, dv[j] * Bv[j] * uv[j]);
            p[j] = h * Cv[j];
        }
        // interleaved tree reduction over the 16 state lanes (4 independent chains)
        #pragma unroll
        for (int st = 8; st > 0; st >>= 1) {
            #pragma unroll
            for (int j = 0; j < 4; j++)
                p[j] += __shfl_xor_sync(0xffffffffu, p[j], st);
        }
        if (n == 0) {
            #pragma unroll
            for (int j = 0; j < 4; j++) {
                int l = l0 + j;
                float r = rrow[l * 1024];
                float sil = r / (1.f + __expf(-r));
                yrow[l * 512] = (p[j] + uv[j] * Dd) * sil;
            }
        }
    }
}

// ---------------- LayerNorm(256) + residual into s (warp-shuffle) ----------------
__global__ void lnres_kernel(const float* __restrict__ yin, const float* __restrict__ g,
                             const float* __restrict__ bb) {
    int row = blockIdx.x;
    int c = threadIdx.x;
    __shared__ float ws1[8], ws2[8];
    float v = yin[row * 256 + c];
    float s1 = v;
    #pragma unroll
    for (int st = 16; st > 0; st >>= 1) s1 += __shfl_xor_sync(0xffffffffu, s1, st);
    if ((c & 31) == 0) ws1[c >> 5] = s1;
    __syncthreads();
    float tot = 0.f;
    #pragma unroll
    for (int k = 0; k < 8; k++) tot += ws1[k];
    float mean = tot * (1.f / 256.f);
    float dv = v - mean;
    float s2 = dv * dv;
    #pragma unroll
    for (int st = 16; st > 0; st >>= 1) s2 += __shfl_xor_sync(0xffffffffu, s2, st);
    if ((c & 31) == 0) ws2[c >> 5] = s2;
    __syncthreads();
    float var = 0.f;
    #pragma unroll
    for (int k = 0; k < 8; k++) var += ws2[k];
    var *= (1.f / 256.f);
    g_s[row * 256 + c] += dv * rsqrtf(var + EPSV) * g[c] + bb[c];
}

// ---------------- mean pool over L, two-stage ----------------
__global__ void pool_partial_kernel() {
    int b = blockIdx.x;
    int chunk = blockIdx.y;
    int c = threadIdx.x;
    float acc = 0.f;
    int l0 = chunk * 64;
    for (int l = l0; l < l0 + 64; l++) acc += g_s[(b * 1024 + l) * 256 + c];
    g_poolp[(b * 16 + chunk) * 256 + c] = acc;
}

// ---------------- head LN (reduces partials) ----------------
__global__ void headln_kernel(const float* __restrict__ nw, const float* __restrict__ nb) {
    int b = blockIdx.x;
    int c = threadIdx.x;
    __shared__ float red[256];
    float v = 0.f;
    #pragma unroll
    for (int k = 0; k < 16; k++) v += g_poolp[(b * 16 + k) * 256 + c];
    v *= (1.f / 1024.f);
    red[c] = v;
    __syncthreads();
    for (int st = 128; st > 0; st >>= 1) {
        if (c < st) red[c] += red[c + st];
        __syncthreads();
    }
    float mean = red[0] * (1.f / 256.f);
    __syncthreads();
    float dv = v - mean;
    red[c] = dv * dv;
    __syncthreads();
    for (int st = 128; st > 0; st >>= 1) {
        if (c < st) red[c] += red[c + st];
        __syncthreads();
    }
    float var = red[0] * (1.f / 256.f);
    g_pool[b * 256 + c] = dv * rsqrtf(var + EPSV) * nw[c] + nb[c];
}

// ---------------- FC: logits (vectorized) ----------------
__global__ void fc_kernel(const float* __restrict__ fcw, const float* __restrict__ fcb,
                          float* __restrict__ out) {
    int idx = blockIdx.x * blockDim.x + threadIdx.x;
    if (idx >= 4000) return;
    int b = idx / 1000;
    int nn = idx % 1000;
    const float4* wp = (const float4*)(fcw + nn * 256);
    const float4* pp = (const float4*)(g_pool + b * 256);
    float acc = fcb[nn];
    #pragma unroll 8
    for (int k = 0; k < 64; k++) {
        float4 w4 = wp[k], p4 = pp[k];
        acc = fmaf(w4.x, p4.x, acc);
        acc = fmaf(w4.y, p4.y, acc);
        acc = fmaf(w4.z, p4.z, acc);
        acc = fmaf(w4.w, p4.w, acc);
    }
    out[idx] = acc;
}

// ---------------- softmax over 1000 ----------------
__global__ void softmax_kernel(const float* __restrict__ logits, float* __restrict__ out) {
    int b = blockIdx.x;
    int t = threadIdx.x;
    __shared__ float red[256];
    float mx = -1e30f;
    for (int i = t; i < 1000; i += 256) mx = fmaxf(mx, logits[b * 1000 + i]);
    red[t] = mx;
    __syncthreads();
    for (int st = 128; st > 0; st >>= 1) {
        if (t < st) red[t] = fmaxf(red[t], red[t + st]);
        __syncthreads();
    }
    mx = red[0];
    __syncthreads();
    float sum = 0.f;
    for (int i = t; i < 1000; i += 256) sum += expf(logits[b * 1000 + i] - mx);
    red[t] = sum;
    __syncthreads();
    for (int st = 128; st > 0; st >>= 1) {
        if (t < st) red[t] += red[t + st];
        __syncthreads();
    }
    float inv = 1.f / red[0];
    for (int i = t; i < 1000; i += 256)
        out[b * 1000 + i] = expf(logits[b * 1000 + i] - mx) * inv;
}

// ---------------- host ----------------
template <int BM, int BN>
static void launch_gemm4(const float* A, int lda, const float* W, const float* bias,
                         const float* bng, const float* bnb, float* C, int ldc,
                         int M, int N, int K, int act) {
    dim3 grid(N / BN, M / BM);
    gemm4_kernel<BM, BN><<<grid, 256>>>(A, lda, W, bias, bng, bnb, C, ldc, K, act);
}

extern "C" void kernel_launch(void* const* d_in, const int* in_sizes, int n_in,
                              void* d_out, int out_size) {
    const float* x    = (const float*)d_in[0];
    const float* c1w  = (const float*)d_in[1];
    const float* c1b  = (const float*)d_in[2];
    const float* g1   = (const float*)d_in[3];
    const float* b1   = (const float*)d_in[4];
    const float* c2w  = (const float*)d_in[5];
    const float* c2b  = (const float*)d_in[6];
    const float* g2   = (const float*)d_in[7];
    const float* b2   = (const float*)d_in[8];
    const float* pw   = (const float*)d_in[9];
    const float* pb   = (const float*)d_in[10];
    const float* g3   = (const float*)d_in[11];
    const float* b3   = (const float*)d_in[12];
    const float* ipw  = (const float*)d_in[13];
    const float* ipb  = (const float*)d_in[14];
    const float* cw   = (const float*)d_in[15];
    const float* cb   = (const float*)d_in[16];
    const float* xpw  = (const float*)d_in[17];
    const float* dpw  = (const float*)d_in[18];
    const float* dpb  = (const float*)d_in[19];
    const float* alog = (const float*)d_in[20];
    const float* dssm = (const float*)d_in[21];
    const float* opw  = (const float*)d_in[22];
    const float* opb  = (const float*)d_in[23];
    const float* lnw  = (const float*)d_in[24];
    const float* lnb  = (const float*)d_in[25];
    const float* nw   = (const float*)d_in[26];
    const float* nb   = (const float*)d_in[27];
    const float* fcw  = (const float*)d_in[28];
    const float* fcb  = (const float*)d_in[29];

    float *im, *h2, *s, *xr, *xl, *xdbl, *delta, *y, *y2;
    cudaGetSymbolAddress((void**)&im, g_im);
    cudaGetSymbolAddress((void**)&h2, g_h2);
    cudaGetSymbolAddress((void**)&s, g_s);
    cudaGetSymbolAddress((void**)&xr, g_xr);
    cudaGetSymbolAddress((void**)&xl, g_xl);
    cudaGetSymbolAddress((void**)&xdbl, g_xdbl);
    cudaGetSymbolAddress((void**)&delta, g_delta);
    cudaGetSymbolAddress((void**)&y, g_y);
    cudaGetSymbolAddress((void**)&y2, g_y2);

    // conv stem
    conv1_kernel<<<8192, 256>>>(x, c1w, c1b, g1, b1);
    im2col2_kernel<<<73728, 256>>>();
    launch_gemm4<128, 128>(im, 1152, c2w, c2b, g2, b2, h2, 256, 16384, 256, 1152, 2);
    im2col3_kernel<<<16384, 256>>>();
    launch_gemm4<64, 128>(im, 1024, pw, pb, g3, b3, s, 256, 4096, 256, 1024, 2);

    // mamba blocks
    for (int i = 0; i < 4; i++) {
        launch_gemm4<128, 128>(s, 256, ipw + i * 1024 * 256, ipb + i * 1024, 0, 0,
                               xr, 1024, 4096, 1024, 256, 0);
        dwconv_kernel<<<8192, 256>>>(cw + i * 512 * 4, cb + i * 512);
        launch_gemm4<64, 64>(xl, 512, xpw + i * 64 * 512, 0, 0, 0,
                             xdbl, 64, 4096, 64, 512, 0);
        launch_gemm4<128, 64>(xdbl, 64, dpw + i * 512 * 32, dpb + i * 512, 0, 0,
                              delta, 512, 4096, 512, 32, 1);
        scan_kernel<<<256, 128>>>(alog + i * 512 * 16, dssm + i * 512);
        launch_gemm4<64, 128>(y, 512, opw + i * 256 * 512, opb + i * 256, 0, 0,
                              y2, 256, 4096, 256, 512, 0);
        lnres_kernel<<<4096, 256>>>(y2, lnw + i * 256, lnb + i * 256);
    }

    // head
    dim3 pgrid(4, 16);
    pool_partial_kernel<<<pgrid, 256>>>();
    headln_kernel<<<4, 256>>>(nw, nb);
    float* out = (float*)d_out;
    fc_kernel<<<16, 256>>>(fcw, fcb, out);
    softmax_kernel<<<4, 256>>>(out, out + 4000);
}